// round 4
// baseline (speedup 1.0000x reference)
#include <cuda_runtime.h>

// Problem constants
#define BB 256
#define NT 196          // tokens
#define CC 784
#define HH 4
#define DD 196          // head dim (== NT)
#define MM (BB*NT)      // 50176 rows for the projections
#define BH (BB*HH)      // 1024 (batch*heads)

// ---------------------------------------------------------------------------
// Scratch (static __device__ — no allocations allowed)
// ---------------------------------------------------------------------------
__device__ float g_q[(size_t)BH*NT*DD];   // (b,h,n,d)
__device__ float g_k[(size_t)BH*NT*DD];
__device__ float g_v[(size_t)BH*NT*DD];
__device__ float g_s[(size_t)BH*NT*NT];   // scores -> attn (in place)
__device__ float g_o[(size_t)BB*NT*CC];   // (b, n, h*d)  row-major for final proj
__device__ float g_cp[(size_t)HH*NT*DD];  // cp[h][p][k]

// ---------------------------------------------------------------------------
// cp[h][p][k] = rel_h[h][k][p/14] + rel_w[h][k][p%14]
// ---------------------------------------------------------------------------
__global__ void cp_kernel(const float* __restrict__ rel_h,
                          const float* __restrict__ rel_w) {
    int idx = blockIdx.x * blockDim.x + threadIdx.x;
    if (idx >= HH * NT * DD) return;
    int k = idx % DD;
    int p = (idx / DD) % NT;
    int h = idx / (DD * NT);
    g_cp[idx] = rel_h[(h * DD + k) * 14 + p / 14]
              + rel_w[(h * DD + k) * 14 + p % 14];
}

// ---------------------------------------------------------------------------
// Projection GEMM:  out = A(M x 784) @ W(784 x 784)^T + bias
// Tile 128x112, BK=16, 256 threads, 8x7 micro-tile.
// MODE 0: QKV — blockIdx.z selects (W,b); A = x (argument); scatter-store
//         to (b,h,n,d) scratch.
// MODE 1: final — A = g_o (device symbol, referenced IN-KERNEL ONLY);
//         plain row-major store into d_out.
// ---------------------------------------------------------------------------
template <int MODE>
__global__ __launch_bounds__(256)
void proj_kernel(const float* __restrict__ Ain,
                 const float* __restrict__ W0, const float* __restrict__ W1,
                 const float* __restrict__ W2,
                 const float* __restrict__ b0, const float* __restrict__ b1,
                 const float* __restrict__ b2,
                 float* __restrict__ outPlain) {
    const float* A;
    const float* W;
    const float* bias;
    float* dst = outPlain;
    if (MODE == 0) {
        int z = blockIdx.z;
        A    = Ain;
        W    = (z == 0) ? W0 : (z == 1) ? W1 : W2;
        bias = (z == 0) ? b0 : (z == 1) ? b1 : b2;
        dst  = (z == 0) ? g_q : (z == 1) ? g_k : g_v;
    } else {
        A = g_o;          // device symbol — valid address only inside kernel
        W = W0; bias = b0;
    }

    __shared__ float As[16][129];   // [k][row], padded
    __shared__ float Bs[16][113];   // [k][col], padded

    const int tid = threadIdx.x;
    const int ty  = tid >> 4;      // 0..15
    const int tx  = tid & 15;      // 0..15
    const int m0  = blockIdx.x * 128;
    const int n0  = blockIdx.y * 112;

    float acc[8][7];
#pragma unroll
    for (int i = 0; i < 8; i++)
#pragma unroll
        for (int j = 0; j < 7; j++) acc[i][j] = 0.f;

    for (int k0 = 0; k0 < 784; k0 += 16) {
        // load A tile: 128 rows x 16 k  (512 float4)
#pragma unroll
        for (int s = 0; s < 2; s++) {
            int i4  = tid + s * 256;            // 0..511
            int row = i4 >> 2;
            int kv  = (i4 & 3) * 4;
            float4 v = *(const float4*)&A[(size_t)(m0 + row) * 784 + k0 + kv];
            As[kv + 0][row] = v.x;
            As[kv + 1][row] = v.y;
            As[kv + 2][row] = v.z;
            As[kv + 3][row] = v.w;
        }
        // load W tile: 112 rows x 16 k  (448 float4)
#pragma unroll
        for (int s = 0; s < 2; s++) {
            int i4 = tid + s * 256;
            if (i4 < 448) {
                int row = i4 >> 2;
                int kv  = (i4 & 3) * 4;
                float4 v = *(const float4*)&W[(size_t)(n0 + row) * 784 + k0 + kv];
                Bs[kv + 0][row] = v.x;
                Bs[kv + 1][row] = v.y;
                Bs[kv + 2][row] = v.z;
                Bs[kv + 3][row] = v.w;
            }
        }
        __syncthreads();

#pragma unroll
        for (int kk = 0; kk < 16; kk++) {
            float a[8], b[7];
#pragma unroll
            for (int i = 0; i < 8; i++) a[i] = As[kk][ty * 8 + i];
#pragma unroll
            for (int j = 0; j < 7; j++) b[j] = Bs[kk][tx * 7 + j];
#pragma unroll
            for (int i = 0; i < 8; i++)
#pragma unroll
                for (int j = 0; j < 7; j++) acc[i][j] += a[i] * b[j];
        }
        __syncthreads();
    }

    // epilogue
#pragma unroll
    for (int i = 0; i < 8; i++) {
        int m = m0 + ty * 8 + i;
#pragma unroll
        for (int j = 0; j < 7; j++) {
            int jg = n0 + tx * 7 + j;
            float val = acc[i][j] + bias[jg];
            if (MODE == 0) {
                int bi = m / NT, n = m % NT;
                int h  = jg / DD, dd = jg % DD;
                dst[(((size_t)bi * HH + h) * NT + n) * DD + dd] = val;
            } else {
                dst[(size_t)m * 784 + jg] = val;
            }
        }
    }
}

// ---------------------------------------------------------------------------
// Scores:  S = Q K^T / 14  +  Cp_h @ Q       (per (b,h): 196x196)
// Tile 98x98, BK=14, 196 threads, 7x7 micro-tile.
// ---------------------------------------------------------------------------
__global__ __launch_bounds__(196)
void scores_kernel() {
    const int batch = blockIdx.z;          // 0..1023 = bi*4 + h
    const int h     = batch & 3;
    const int i0    = blockIdx.y * 98;
    const int j0    = blockIdx.x * 98;

    const float* Q  = g_q  + (size_t)batch * NT * DD;
    const float* K  = g_k  + (size_t)batch * NT * DD;
    const float* CP = g_cp + (size_t)h * NT * DD;

    __shared__ float As[14][98];
    __shared__ float Bs[14][98];

    const int t  = threadIdx.x;
    const int ty = t / 14;
    const int tx = t % 14;

    float acc[7][7];
#pragma unroll
    for (int i = 0; i < 7; i++)
#pragma unroll
        for (int j = 0; j < 7; j++) acc[i][j] = 0.f;

    // ---- term 1: Q K^T ----
    for (int k0 = 0; k0 < 196; k0 += 14) {
#pragma unroll
        for (int s = 0; s < 7; s++) {
            int idx = t + s * 196;          // 0..1371
            int row = idx / 14, kk = idx % 14;
            As[kk][row] = Q[(i0 + row) * 196 + k0 + kk];
            Bs[kk][row] = K[(j0 + row) * 196 + k0 + kk];
        }
        __syncthreads();
#pragma unroll
        for (int kk = 0; kk < 14; kk++) {
            float a[7], b[7];
#pragma unroll
            for (int i = 0; i < 7; i++) a[i] = As[kk][ty * 7 + i];
#pragma unroll
            for (int j = 0; j < 7; j++) b[j] = Bs[kk][tx * 7 + j];
#pragma unroll
            for (int i = 0; i < 7; i++)
#pragma unroll
                for (int j = 0; j < 7; j++) acc[i][j] += a[i] * b[j];
        }
        __syncthreads();
    }

    const float inv_sqrt_d = 1.0f / 14.0f;
#pragma unroll
    for (int i = 0; i < 7; i++)
#pragma unroll
        for (int j = 0; j < 7; j++) acc[i][j] *= inv_sqrt_d;

    // ---- term 2: Cp @ Q  (contraction over token axis of Q) ----
    for (int k0 = 0; k0 < 196; k0 += 14) {
#pragma unroll
        for (int s = 0; s < 7; s++) {
            int idx = t + s * 196;
            int row = idx / 14, kk = idx % 14;
            As[kk][row] = CP[(i0 + row) * 196 + k0 + kk];
        }
#pragma unroll
        for (int s = 0; s < 7; s++) {
            int idx = t + s * 196;
            int row = idx / 98, col = idx % 98;   // row: 0..13
            Bs[row][col] = Q[(k0 + row) * 196 + j0 + col];
        }
        __syncthreads();
#pragma unroll
        for (int kk = 0; kk < 14; kk++) {
            float a[7], b[7];
#pragma unroll
            for (int i = 0; i < 7; i++) a[i] = As[kk][ty * 7 + i];
#pragma unroll
            for (int j = 0; j < 7; j++) b[j] = Bs[kk][tx * 7 + j];
#pragma unroll
            for (int i = 0; i < 7; i++)
#pragma unroll
                for (int j = 0; j < 7; j++) acc[i][j] += a[i] * b[j];
        }
        __syncthreads();
    }

    float* S = g_s + (size_t)batch * NT * NT;
#pragma unroll
    for (int i = 0; i < 7; i++)
#pragma unroll
        for (int j = 0; j < 7; j++)
            S[(i0 + ty * 7 + i) * 196 + j0 + tx * 7 + j] = acc[i][j];
}

// ---------------------------------------------------------------------------
// Row-wise softmax over g_s (rows of length 196), one warp per row.
// ---------------------------------------------------------------------------
__global__ __launch_bounds__(256)
void softmax_kernel() {
    int row  = blockIdx.x * 8 + (threadIdx.x >> 5);
    int lane = threadIdx.x & 31;
    if (row >= BH * NT) return;
    float* S = g_s + (size_t)row * 196;

    float vals[7];
    float mx = -1e30f;
#pragma unroll
    for (int s = 0; s < 7; s++) {
        int j = lane + 32 * s;
        vals[s] = (j < 196) ? S[j] : -1e30f;
        mx = fmaxf(mx, vals[s]);
    }
#pragma unroll
    for (int off = 16; off > 0; off >>= 1)
        mx = fmaxf(mx, __shfl_xor_sync(0xffffffffu, mx, off));

    float sum = 0.f;
#pragma unroll
    for (int s = 0; s < 7; s++) {
        vals[s] = expf(vals[s] - mx);
        sum += vals[s];
    }
#pragma unroll
    for (int off = 16; off > 0; off >>= 1)
        sum += __shfl_xor_sync(0xffffffffu, sum, off);

    float inv = 1.0f / sum;
#pragma unroll
    for (int s = 0; s < 7; s++) {
        int j = lane + 32 * s;
        if (j < 196) S[j] = vals[s] * inv;
    }
}

// ---------------------------------------------------------------------------
// attn @ V, store head-merged (b, n, h*d) row-major into g_o.
// Tile 98x98, BK=14, 196 threads, 7x7 micro-tile.
// ---------------------------------------------------------------------------
__global__ __launch_bounds__(196)
void av_kernel() {
    const int batch = blockIdx.z;
    const int bi = batch >> 2;
    const int h  = batch & 3;
    const int i0 = blockIdx.y * 98;   // token rows
    const int d0 = blockIdx.x * 98;   // head-dim cols

    const float* Sb = g_s + (size_t)batch * NT * NT;
    const float* V  = g_v + (size_t)batch * NT * DD;

    __shared__ float As[14][98];
    __shared__ float Bs[14][98];

    const int t  = threadIdx.x;
    const int ty = t / 14;
    const int tx = t % 14;

    float acc[7][7];
#pragma unroll
    for (int i = 0; i < 7; i++)
#pragma unroll
        for (int j = 0; j < 7; j++) acc[i][j] = 0.f;

    for (int k0 = 0; k0 < 196; k0 += 14) {
#pragma unroll
        for (int s = 0; s < 7; s++) {
            int idx = t + s * 196;
            int row = idx / 14, kk = idx % 14;
            As[kk][row] = Sb[(i0 + row) * 196 + k0 + kk];
        }
#pragma unroll
        for (int s = 0; s < 7; s++) {
            int idx = t + s * 196;
            int row = idx / 98, col = idx % 98;
            Bs[row][col] = V[(k0 + row) * 196 + d0 + col];
        }
        __syncthreads();
#pragma unroll
        for (int kk = 0; kk < 14; kk++) {
            float a[7], b[7];
#pragma unroll
            for (int i = 0; i < 7; i++) a[i] = As[kk][ty * 7 + i];
#pragma unroll
            for (int j = 0; j < 7; j++) b[j] = Bs[kk][tx * 7 + j];
#pragma unroll
            for (int i = 0; i < 7; i++)
#pragma unroll
                for (int j = 0; j < 7; j++) acc[i][j] += a[i] * b[j];
        }
        __syncthreads();
    }

#pragma unroll
    for (int i = 0; i < 7; i++) {
        int n = i0 + ty * 7 + i;
#pragma unroll
        for (int j = 0; j < 7; j++) {
            int dd = d0 + tx * 7 + j;
            g_o[((size_t)bi * NT + n) * CC + h * DD + dd] = acc[i][j];
        }
    }
}

// ---------------------------------------------------------------------------
// kernel_launch
// ---------------------------------------------------------------------------
extern "C" void kernel_launch(void* const* d_in, const int* in_sizes, int n_in,
                              void* d_out, int out_size) {
    const float* x     = (const float*)d_in[0];
    const float* Wq    = (const float*)d_in[1];
    const float* bq    = (const float*)d_in[2];
    const float* Wk    = (const float*)d_in[3];
    const float* bk    = (const float*)d_in[4];
    const float* Wv    = (const float*)d_in[5];
    const float* bv    = (const float*)d_in[6];
    const float* Wo    = (const float*)d_in[7];
    const float* bo    = (const float*)d_in[8];
    const float* rel_h = (const float*)d_in[9];
    const float* rel_w = (const float*)d_in[10];
    float* out = (float*)d_out;

    // 1) RPE table
    {
        int n = HH * NT * DD;
        cp_kernel<<<(n + 255) / 256, 256>>>(rel_h, rel_w);
    }
    // 2) QKV projections (z = 0,1,2)
    {
        dim3 grid(MM / 128, CC / 112, 3);
        proj_kernel<0><<<grid, 256>>>(x, Wq, Wk, Wv, bq, bk, bv, nullptr);
    }
    // 3) scores = QK^T/sqrt(d) + Cp@Q
    {
        dim3 grid(2, 2, BH);
        scores_kernel<<<grid, 196>>>();
    }
    // 4) softmax
    {
        int rows = BH * NT;
        softmax_kernel<<<rows / 8, 256>>>();
    }
    // 5) attn @ V  (head-merged store)
    {
        dim3 grid(2, 2, BH);
        av_kernel<<<grid, 196>>>();
    }
    // 6) output projection (A = g_o selected inside the kernel)
    {
        dim3 grid(MM / 128, CC / 112, 1);
        proj_kernel<1><<<grid, 256>>>(nullptr, Wo, nullptr, nullptr, bo,
                                      nullptr, nullptr, out);
    }
}

// round 7
// speedup vs baseline: 1.1774x; 1.1774x over previous
#include <cuda_runtime.h>
#include <cstdint>

// Problem constants
#define BB 256
#define NT 196
#define CC 784
#define HH 4
#define DD 196
#define MM (BB*NT)      // 50176
#define BH (BB*HH)      // 1024

// ---------------------------------------------------------------------------
// Scratch (static __device__ — no allocations allowed). All plain fp32.
// ---------------------------------------------------------------------------
__device__ float g_q[(size_t)BH*NT*DD];   // (b,h,n,d)
__device__ float g_k[(size_t)BH*NT*DD];
__device__ float g_v[(size_t)BH*NT*DD];
__device__ float g_s[(size_t)BH*NT*NT];   // scores -> attn (in place)
__device__ float g_o[(size_t)BB*NT*CC];   // (b,n,h*d)
__device__ float g_cp[(size_t)HH*NT*DD];  // cp[h][p][k]

// ---------------------------------------------------------------------------
// tf32 split helpers (3xTF32 scheme)
// ---------------------------------------------------------------------------
__device__ __forceinline__ void split1(float v, uint32_t& hi, uint32_t& lo) {
    uint32_t h; asm("cvt.rna.tf32.f32 %0, %1;" : "=r"(h) : "f"(v));
    float r = v - __uint_as_float(h);
    uint32_t l; asm("cvt.rna.tf32.f32 %0, %1;" : "=r"(l) : "f"(r));
    hi = h; lo = l;
}
__device__ __forceinline__ void split4(float4 v, uint4& hi, uint4& lo) {
    split1(v.x, hi.x, lo.x); split1(v.y, hi.y, lo.y);
    split1(v.z, hi.z, lo.z); split1(v.w, hi.w, lo.w);
}
__device__ __forceinline__ void mma8(float* c, const uint32_t* a,
                                     uint32_t b0, uint32_t b1) {
    asm volatile("mma.sync.aligned.m16n8k8.row.col.f32.tf32.tf32.f32 "
                 "{%0,%1,%2,%3}, {%4,%5,%6,%7}, {%8,%9}, {%0,%1,%2,%3};"
                 : "+f"(c[0]), "+f"(c[1]), "+f"(c[2]), "+f"(c[3])
                 : "r"(a[0]), "r"(a[1]), "r"(a[2]), "r"(a[3]),
                   "r"(b0), "r"(b1));
}

// Dynamic smem word layout (uint32_t units):
//   As[buf][part][128][20] : parts = hi(0), lo(1)
//   Bs[buf][part][112][20]
#define AS_WORDS (128*20)
#define BS_WORDS (112*20)
#define BS_BASE  (4*AS_WORDS)
#define SMEM_BYTES ((4*AS_WORDS + 4*BS_WORDS)*4)   // 76800
__device__ __forceinline__ uint32_t* As_p(uint32_t* s, int buf, int part) {
    return s + (buf*2 + part) * AS_WORDS;
}
__device__ __forceinline__ uint32_t* Bs_p(uint32_t* s, int buf, int part) {
    return s + BS_BASE + (buf*2 + part) * BS_WORDS;
}

// One BK=16 chunk, 3xTF32. Warp tile 32(M) x 56(N): 2 m16 x 7 n8 frags.
__device__ __forceinline__ void gemm_bk16_3x(const uint32_t* Ah,
                                             const uint32_t* Al,
                                             const uint32_t* Bh,
                                             const uint32_t* Bl,
                                             int wm, int wn, int g, int t,
                                             float acc[2][7][4]) {
#pragma unroll
    for (int kk = 0; kk < 2; ++kk) {
        const int kb = kk * 8;
        uint32_t ah[2][4], al[2][4];
#pragma unroll
        for (int mt = 0; mt < 2; ++mt) {
            int r0 = (wm + mt * 16 + g) * 20;
            int r1 = (wm + mt * 16 + g + 8) * 20;
            ah[mt][0] = Ah[r0 + kb + t];
            ah[mt][1] = Ah[r1 + kb + t];
            ah[mt][2] = Ah[r0 + kb + t + 4];
            ah[mt][3] = Ah[r1 + kb + t + 4];
            al[mt][0] = Al[r0 + kb + t];
            al[mt][1] = Al[r1 + kb + t];
            al[mt][2] = Al[r0 + kb + t + 4];
            al[mt][3] = Al[r1 + kb + t + 4];
        }
#pragma unroll
        for (int nt = 0; nt < 7; ++nt) {
            int nc = (wn + nt * 8 + g) * 20;
            uint32_t b0h = Bh[nc + kb + t], b1h = Bh[nc + kb + t + 4];
            uint32_t b0l = Bl[nc + kb + t], b1l = Bl[nc + kb + t + 4];
#pragma unroll
            for (int mt = 0; mt < 2; ++mt) {
                mma8(acc[mt][nt], ah[mt], b0h, b1h);   // hi*hi
                mma8(acc[mt][nt], ah[mt], b0l, b1l);   // hi*lo
                mma8(acc[mt][nt], al[mt], b0h, b1h);   // lo*hi
            }
        }
    }
}

// Guarded row-major float4 load from a 196-wide matrix (row pre-clamped).
__device__ __forceinline__ float4 load_row196(const float* P, int row, int k,
                                              bool kval) {
    if (kval) return *(const float4*)&P[(size_t)row * 196 + k];
    return make_float4(0.f, 0.f, 0.f, 0.f);
}

// Transposed tile gather: pv = P[k0+k][j0+n] for a 16k x 112n tile, guarded.
__device__ __forceinline__ void load_trans196(const float* P, int j0, int k0,
                                              int tid, float* pv) {
#pragma unroll
    for (int s = 0; s < 2; ++s) {
        int i4 = tid + s * 256;
        if (i4 < 448) {
            int krow = k0 + i4 / 28;
            int nq = (i4 % 28) * 4;
            int n = j0 + nq;
            if (krow < 196 && n + 3 < 196) {
                float4 f = *(const float4*)&P[(size_t)krow * 196 + n];
                pv[s*4+0] = f.x; pv[s*4+1] = f.y;
                pv[s*4+2] = f.z; pv[s*4+3] = f.w;
            } else {
#pragma unroll
                for (int j = 0; j < 4; ++j)
                    pv[s*4+j] = (krow < 196 && n + j < 196)
                                ? P[(size_t)krow * 196 + n + j] : 0.f;
            }
        }
    }
}
__device__ __forceinline__ void store_trans(uint32_t* Bh, uint32_t* Bl,
                                            int tid, const float* pv) {
#pragma unroll
    for (int s = 0; s < 2; ++s) {
        int i4 = tid + s * 256;
        if (i4 < 448) {
            int krow = i4 / 28, nq = (i4 % 28) * 4;
#pragma unroll
            for (int j = 0; j < 4; ++j) {
                uint32_t h, l; split1(pv[s*4+j], h, l);
                Bh[(nq + j) * 20 + krow] = h;
                Bl[(nq + j) * 20 + krow] = l;
            }
        }
    }
}

// cp[h][p][k] = rel_h[h][k][p/14] + rel_w[h][k][p%14]
__global__ void cp_kernel(const float* __restrict__ rel_h,
                          const float* __restrict__ rel_w) {
    int idx = blockIdx.x * blockDim.x + threadIdx.x;
    if (idx >= HH * NT * DD) return;
    int k = idx % DD;
    int p = (idx / DD) % NT;
    int h = idx / (DD * NT);
    g_cp[idx] = rel_h[(h * DD + k) * 14 + p / 14]
              + rel_w[(h * DD + k) * 14 + p % 14];
}

// ---------------------------------------------------------------------------
// Projection GEMM (3xTF32): out = A(M x 784) @ W(784 x 784)^T + bias
// Block 128x112, BK=16, 256 threads (8 warps 4x2), double-buffered hi/lo.
// MODE 0: A=x, z selects (W,bias,dst q/k/v) with head-split scatter.
// MODE 1: A=g_o, plain store to d_out.
// ---------------------------------------------------------------------------
template <int MODE>
__global__ __launch_bounds__(256)
void proj_tf32x3(const float* __restrict__ Ain,
                 const float* __restrict__ W0, const float* __restrict__ W1,
                 const float* __restrict__ W2,
                 const float* __restrict__ b0p, const float* __restrict__ b1p,
                 const float* __restrict__ b2p, float* __restrict__ outp) {
    extern __shared__ uint32_t sm[];
    const int tid = threadIdx.x;
    const int z = (MODE == 0) ? blockIdx.z : 0;
    const float* A = (MODE == 0) ? Ain : g_o;
    const float* W = (MODE == 0) ? ((z == 0) ? W0 : (z == 1) ? W1 : W2) : W0;
    const float* bias = (MODE == 0) ? ((z == 0) ? b0p : (z == 1) ? b1p : b2p)
                                    : b0p;
    float* dst = (MODE == 0) ? ((z == 0) ? g_q : (z == 1) ? g_k : g_v) : outp;

    const int m0 = blockIdx.x * 128, n0 = blockIdx.y * 112;
    const int w = tid >> 5, lane = tid & 31;
    const int wm = (w >> 1) * 32, wn = (w & 1) * 56;
    const int g = lane >> 2, t = lane & 3;

    const int rowA0 = tid >> 2, kq = (tid & 3) * 4;
    const int rowA1 = (tid + 256) >> 2;
    const bool hasB1 = (tid + 256) < 448;

    float acc[2][7][4];
#pragma unroll
    for (int i = 0; i < 2; i++)
#pragma unroll
        for (int j = 0; j < 7; j++)
#pragma unroll
            for (int c = 0; c < 4; c++) acc[i][j][c] = 0.f;

    // prologue: tile 0 -> buf 0
    {
        float4 va0 = *(const float4*)&A[(size_t)(m0 + rowA0) * 784 + kq];
        float4 va1 = *(const float4*)&A[(size_t)(m0 + rowA1) * 784 + kq];
        float4 vb0 = *(const float4*)&W[(size_t)(n0 + rowA0) * 784 + kq];
        uint4 h, l;
        split4(va0, h, l);
        *(uint4*)&As_p(sm,0,0)[rowA0*20 + kq] = h;
        *(uint4*)&As_p(sm,0,1)[rowA0*20 + kq] = l;
        split4(va1, h, l);
        *(uint4*)&As_p(sm,0,0)[rowA1*20 + kq] = h;
        *(uint4*)&As_p(sm,0,1)[rowA1*20 + kq] = l;
        split4(vb0, h, l);
        *(uint4*)&Bs_p(sm,0,0)[rowA0*20 + kq] = h;
        *(uint4*)&Bs_p(sm,0,1)[rowA0*20 + kq] = l;
        if (hasB1) {
            float4 vb1 = *(const float4*)&W[(size_t)(n0 + rowA1) * 784 + kq];
            split4(vb1, h, l);
            *(uint4*)&Bs_p(sm,0,0)[rowA1*20 + kq] = h;
            *(uint4*)&Bs_p(sm,0,1)[rowA1*20 + kq] = l;
        }
    }
    __syncthreads();

    for (int it = 0; it < 49; ++it) {
        const int bf = it & 1;
        float4 va0, va1, vb0, vb1;
        if (it < 48) {
            int k0 = (it + 1) * 16;
            va0 = *(const float4*)&A[(size_t)(m0 + rowA0) * 784 + k0 + kq];
            va1 = *(const float4*)&A[(size_t)(m0 + rowA1) * 784 + k0 + kq];
            vb0 = *(const float4*)&W[(size_t)(n0 + rowA0) * 784 + k0 + kq];
            if (hasB1)
                vb1 = *(const float4*)&W[(size_t)(n0 + rowA1) * 784 + k0 + kq];
        }
        gemm_bk16_3x(As_p(sm,bf,0), As_p(sm,bf,1),
                     Bs_p(sm,bf,0), Bs_p(sm,bf,1), wm, wn, g, t, acc);
        if (it < 48) {
            const int nb = bf ^ 1;
            uint4 h, l;
            split4(va0, h, l);
            *(uint4*)&As_p(sm,nb,0)[rowA0*20 + kq] = h;
            *(uint4*)&As_p(sm,nb,1)[rowA0*20 + kq] = l;
            split4(va1, h, l);
            *(uint4*)&As_p(sm,nb,0)[rowA1*20 + kq] = h;
            *(uint4*)&As_p(sm,nb,1)[rowA1*20 + kq] = l;
            split4(vb0, h, l);
            *(uint4*)&Bs_p(sm,nb,0)[rowA0*20 + kq] = h;
            *(uint4*)&Bs_p(sm,nb,1)[rowA0*20 + kq] = l;
            if (hasB1) {
                split4(vb1, h, l);
                *(uint4*)&Bs_p(sm,nb,0)[rowA1*20 + kq] = h;
                *(uint4*)&Bs_p(sm,nb,1)[rowA1*20 + kq] = l;
            }
        }
        __syncthreads();
    }

    // epilogue
#pragma unroll
    for (int mt = 0; mt < 2; ++mt) {
#pragma unroll
        for (int nt = 0; nt < 7; ++nt) {
            int col = n0 + wn + nt * 8 + 2 * t;
            float bv0 = bias[col], bv1 = bias[col + 1];
#pragma unroll
            for (int half = 0; half < 2; ++half) {
                int row = m0 + wm + mt * 16 + g + half * 8;
                float v0 = acc[mt][nt][half * 2 + 0] + bv0;
                float v1 = acc[mt][nt][half * 2 + 1] + bv1;
                if (MODE == 0) {
                    int bi = row / 196, n = row % 196;
                    int h0 = col / 196, d0c = col % 196;
                    int h1 = (col + 1) / 196, d1c = (col + 1) % 196;
                    dst[(((size_t)bi * 4 + h0) * 196 + n) * 196 + d0c] = v0;
                    dst[(((size_t)bi * 4 + h1) * 196 + n) * 196 + d1c] = v1;
                } else {
                    dst[(size_t)row * 784 + col]     = v0;
                    dst[(size_t)row * 784 + col + 1] = v1;
                }
            }
        }
    }
}

// ---------------------------------------------------------------------------
// Scores (3xTF32): S = Q K^T / 14 + Cp @ Q, per (b,h) 196x196.
// ---------------------------------------------------------------------------
__global__ __launch_bounds__(256)
void scores_tf32x3() {
    extern __shared__ uint32_t sm[];
    const int batch = blockIdx.z, h = batch & 3;
    const int i0 = blockIdx.y * 128, j0 = blockIdx.x * 112;
    const float* Q  = g_q  + (size_t)batch * 196 * 196;
    const float* Kp = g_k  + (size_t)batch * 196 * 196;
    const float* CP = g_cp + (size_t)h * 196 * 196;

    const int tid = threadIdx.x;
    const int w = tid >> 5, lane = tid & 31;
    const int wm = (w >> 1) * 32, wn = (w & 1) * 56;
    const int g = lane >> 2, t = lane & 3;

    const int rowA0 = tid >> 2, kq = (tid & 3) * 4;
    const int rowA1 = (tid + 256) >> 2;
    const bool hasB1 = (tid + 256) < 448;
    const int arA0 = min(i0 + rowA0, 195), arA1 = min(i0 + rowA1, 195);
    const int brA0 = min(j0 + rowA0, 195), brA1 = min(j0 + rowA1, 195);

    float acc[2][7][4];
#pragma unroll
    for (int i = 0; i < 2; i++)
#pragma unroll
        for (int j = 0; j < 7; j++)
#pragma unroll
            for (int c = 0; c < 4; c++) acc[i][j][c] = 0.f;

    // ---------------- pass 1: Q K^T ----------------
    {
        uint4 h4, l4;
        split4(load_row196(Q, arA0, kq, true), h4, l4);
        *(uint4*)&As_p(sm,0,0)[rowA0*20+kq] = h4;
        *(uint4*)&As_p(sm,0,1)[rowA0*20+kq] = l4;
        split4(load_row196(Q, arA1, kq, true), h4, l4);
        *(uint4*)&As_p(sm,0,0)[rowA1*20+kq] = h4;
        *(uint4*)&As_p(sm,0,1)[rowA1*20+kq] = l4;
        split4(load_row196(Kp, brA0, kq, true), h4, l4);
        *(uint4*)&Bs_p(sm,0,0)[rowA0*20+kq] = h4;
        *(uint4*)&Bs_p(sm,0,1)[rowA0*20+kq] = l4;
        if (hasB1) {
            split4(load_row196(Kp, brA1, kq, true), h4, l4);
            *(uint4*)&Bs_p(sm,0,0)[rowA1*20+kq] = h4;
            *(uint4*)&Bs_p(sm,0,1)[rowA1*20+kq] = l4;
        }
    }
    __syncthreads();
    for (int it = 0; it < 13; ++it) {
        const int bf = it & 1;
        float4 va0, va1, vb0, vb1;
        if (it < 12) {
            int k0 = (it + 1) * 16;
            bool kv = (k0 + kq) < 196;
            va0 = load_row196(Q, arA0, k0 + kq, kv);
            va1 = load_row196(Q, arA1, k0 + kq, kv);
            vb0 = load_row196(Kp, brA0, k0 + kq, kv);
            if (hasB1) vb1 = load_row196(Kp, brA1, k0 + kq, kv);
        }
        gemm_bk16_3x(As_p(sm,bf,0), As_p(sm,bf,1),
                     Bs_p(sm,bf,0), Bs_p(sm,bf,1), wm, wn, g, t, acc);
        if (it < 12) {
            const int nb = bf ^ 1;
            uint4 h4, l4;
            split4(va0, h4, l4);
            *(uint4*)&As_p(sm,nb,0)[rowA0*20+kq] = h4;
            *(uint4*)&As_p(sm,nb,1)[rowA0*20+kq] = l4;
            split4(va1, h4, l4);
            *(uint4*)&As_p(sm,nb,0)[rowA1*20+kq] = h4;
            *(uint4*)&As_p(sm,nb,1)[rowA1*20+kq] = l4;
            split4(vb0, h4, l4);
            *(uint4*)&Bs_p(sm,nb,0)[rowA0*20+kq] = h4;
            *(uint4*)&Bs_p(sm,nb,1)[rowA0*20+kq] = l4;
            if (hasB1) {
                split4(vb1, h4, l4);
                *(uint4*)&Bs_p(sm,nb,0)[rowA1*20+kq] = h4;
                *(uint4*)&Bs_p(sm,nb,1)[rowA1*20+kq] = l4;
            }
        }
        __syncthreads();
    }

    const float inv14 = 1.0f / 14.0f;
#pragma unroll
    for (int i = 0; i < 2; i++)
#pragma unroll
        for (int j = 0; j < 7; j++)
#pragma unroll
            for (int c = 0; c < 4; c++) acc[i][j][c] *= inv14;

    __syncthreads();

    // ---------------- pass 2: Cp @ Q ----------------
    {
        float pv[8];
        uint4 h4, l4;
        split4(load_row196(CP, arA0, kq, true), h4, l4);
        *(uint4*)&As_p(sm,0,0)[rowA0*20+kq] = h4;
        *(uint4*)&As_p(sm,0,1)[rowA0*20+kq] = l4;
        split4(load_row196(CP, arA1, kq, true), h4, l4);
        *(uint4*)&As_p(sm,0,0)[rowA1*20+kq] = h4;
        *(uint4*)&As_p(sm,0,1)[rowA1*20+kq] = l4;
        load_trans196(Q, j0, 0, tid, pv);
        store_trans(Bs_p(sm,0,0), Bs_p(sm,0,1), tid, pv);
    }
    __syncthreads();
    for (int it = 0; it < 13; ++it) {
        const int bf = it & 1;
        float4 va0, va1;
        float pv[8];
        if (it < 12) {
            int k0 = (it + 1) * 16;
            bool kv = (k0 + kq) < 196;
            va0 = load_row196(CP, arA0, k0 + kq, kv);
            va1 = load_row196(CP, arA1, k0 + kq, kv);
            load_trans196(Q, j0, k0, tid, pv);
        }
        gemm_bk16_3x(As_p(sm,bf,0), As_p(sm,bf,1),
                     Bs_p(sm,bf,0), Bs_p(sm,bf,1), wm, wn, g, t, acc);
        if (it < 12) {
            const int nb = bf ^ 1;
            uint4 h4, l4;
            split4(va0, h4, l4);
            *(uint4*)&As_p(sm,nb,0)[rowA0*20+kq] = h4;
            *(uint4*)&As_p(sm,nb,1)[rowA0*20+kq] = l4;
            split4(va1, h4, l4);
            *(uint4*)&As_p(sm,nb,0)[rowA1*20+kq] = h4;
            *(uint4*)&As_p(sm,nb,1)[rowA1*20+kq] = l4;
            store_trans(Bs_p(sm,nb,0), Bs_p(sm,nb,1), tid, pv);
        }
        __syncthreads();
    }

    float* S = g_s + (size_t)batch * 196 * 196;
#pragma unroll
    for (int mt = 0; mt < 2; ++mt) {
#pragma unroll
        for (int nt = 0; nt < 7; ++nt) {
            int col = j0 + wn + nt * 8 + 2 * t;
#pragma unroll
            for (int half = 0; half < 2; ++half) {
                int row = i0 + wm + mt * 16 + g + half * 8;
                if (row < 196) {
                    if (col < 196)
                        S[(size_t)row * 196 + col] = acc[mt][nt][half*2+0];
                    if (col + 1 < 196)
                        S[(size_t)row * 196 + col + 1] = acc[mt][nt][half*2+1];
                }
            }
        }
    }
}

// ---------------------------------------------------------------------------
// Row-wise softmax, one warp per row. Plain fp32 in/out.
// ---------------------------------------------------------------------------
__global__ __launch_bounds__(256)
void softmax_kernel() {
    int row  = blockIdx.x * 8 + (threadIdx.x >> 5);
    int lane = threadIdx.x & 31;
    if (row >= BH * NT) return;
    float* S = g_s + (size_t)row * 196;

    float vals[7];
    float mx = -1e30f;
#pragma unroll
    for (int s = 0; s < 7; s++) {
        int j = lane + 32 * s;
        vals[s] = (j < 196) ? S[j] : -1e30f;
        mx = fmaxf(mx, vals[s]);
    }
#pragma unroll
    for (int off = 16; off > 0; off >>= 1)
        mx = fmaxf(mx, __shfl_xor_sync(0xffffffffu, mx, off));

    float sum = 0.f;
#pragma unroll
    for (int s = 0; s < 7; s++) {
        vals[s] = expf(vals[s] - mx);
        sum += vals[s];
    }
#pragma unroll
    for (int off = 16; off > 0; off >>= 1)
        sum += __shfl_xor_sync(0xffffffffu, sum, off);

    float inv = 1.0f / sum;
#pragma unroll
    for (int s = 0; s < 7; s++) {
        int j = lane + 32 * s;
        if (j < 196) S[j] = vals[s] * inv;
    }
}

// ---------------------------------------------------------------------------
// attn @ V (3xTF32), head-merged fp32 store into g_o.
// ---------------------------------------------------------------------------
__global__ __launch_bounds__(256)
void av_tf32x3() {
    extern __shared__ uint32_t sm[];
    const int batch = blockIdx.z;
    const int bi = batch >> 2, h = batch & 3;
    const int i0 = blockIdx.y * 128, d0 = blockIdx.x * 112;
    const float* Sb = g_s + (size_t)batch * 196 * 196;
    const float* V  = g_v + (size_t)batch * 196 * 196;

    const int tid = threadIdx.x;
    const int w = tid >> 5, lane = tid & 31;
    const int wm = (w >> 1) * 32, wn = (w & 1) * 56;
    const int g = lane >> 2, t = lane & 3;

    const int rowA0 = tid >> 2, kq = (tid & 3) * 4;
    const int rowA1 = (tid + 256) >> 2;
    const int arA0 = min(i0 + rowA0, 195), arA1 = min(i0 + rowA1, 195);

    float acc[2][7][4];
#pragma unroll
    for (int i = 0; i < 2; i++)
#pragma unroll
        for (int j = 0; j < 7; j++)
#pragma unroll
            for (int c = 0; c < 4; c++) acc[i][j][c] = 0.f;

    {
        float pv[8];
        uint4 h4, l4;
        split4(load_row196(Sb, arA0, kq, true), h4, l4);
        *(uint4*)&As_p(sm,0,0)[rowA0*20+kq] = h4;
        *(uint4*)&As_p(sm,0,1)[rowA0*20+kq] = l4;
        split4(load_row196(Sb, arA1, kq, true), h4, l4);
        *(uint4*)&As_p(sm,0,0)[rowA1*20+kq] = h4;
        *(uint4*)&As_p(sm,0,1)[rowA1*20+kq] = l4;
        load_trans196(V, d0, 0, tid, pv);
        store_trans(Bs_p(sm,0,0), Bs_p(sm,0,1), tid, pv);
    }
    __syncthreads();
    for (int it = 0; it < 13; ++it) {
        const int bf = it & 1;
        float4 va0, va1;
        float pv[8];
        if (it < 12) {
            int k0 = (it + 1) * 16;
            bool kv = (k0 + kq) < 196;
            va0 = load_row196(Sb, arA0, k0 + kq, kv);
            va1 = load_row196(Sb, arA1, k0 + kq, kv);
            load_trans196(V, d0, k0, tid, pv);
        }
        gemm_bk16_3x(As_p(sm,bf,0), As_p(sm,bf,1),
                     Bs_p(sm,bf,0), Bs_p(sm,bf,1), wm, wn, g, t, acc);
        if (it < 12) {
            const int nb = bf ^ 1;
            uint4 h4, l4;
            split4(va0, h4, l4);
            *(uint4*)&As_p(sm,nb,0)[rowA0*20+kq] = h4;
            *(uint4*)&As_p(sm,nb,1)[rowA0*20+kq] = l4;
            split4(va1, h4, l4);
            *(uint4*)&As_p(sm,nb,0)[rowA1*20+kq] = h4;
            *(uint4*)&As_p(sm,nb,1)[rowA1*20+kq] = l4;
            store_trans(Bs_p(sm,nb,0), Bs_p(sm,nb,1), tid, pv);
        }
        __syncthreads();
    }

#pragma unroll
    for (int mt = 0; mt < 2; ++mt) {
#pragma unroll
        for (int nt = 0; nt < 7; ++nt) {
            int col = d0 + wn + nt * 8 + 2 * t;
#pragma unroll
            for (int half = 0; half < 2; ++half) {
                int row = i0 + wm + mt * 16 + g + half * 8;
                if (row < 196) {
                    if (col < 196)
                        g_o[((size_t)bi * 196 + row) * 784 + h * 196 + col]
                            = acc[mt][nt][half*2+0];
                    if (col + 1 < 196)
                        g_o[((size_t)bi * 196 + row) * 784 + h * 196 + col + 1]
                            = acc[mt][nt][half*2+1];
                }
            }
        }
    }
}

// ---------------------------------------------------------------------------
// kernel_launch
// ---------------------------------------------------------------------------
extern "C" void kernel_launch(void* const* d_in, const int* in_sizes, int n_in,
                              void* d_out, int out_size) {
    const float* x     = (const float*)d_in[0];
    const float* Wq    = (const float*)d_in[1];
    const float* bq    = (const float*)d_in[2];
    const float* Wk    = (const float*)d_in[3];
    const float* bk    = (const float*)d_in[4];
    const float* Wv    = (const float*)d_in[5];
    const float* bv    = (const float*)d_in[6];
    const float* Wo    = (const float*)d_in[7];
    const float* bo    = (const float*)d_in[8];
    const float* rel_h = (const float*)d_in[9];
    const float* rel_w = (const float*)d_in[10];
    float* out = (float*)d_out;

    // allow 76.8 KB dynamic smem (idempotent; not a stream op)
    cudaFuncSetAttribute(proj_tf32x3<0>,
        cudaFuncAttributeMaxDynamicSharedMemorySize, SMEM_BYTES);
    cudaFuncSetAttribute(proj_tf32x3<1>,
        cudaFuncAttributeMaxDynamicSharedMemorySize, SMEM_BYTES);
    cudaFuncSetAttribute(scores_tf32x3,
        cudaFuncAttributeMaxDynamicSharedMemorySize, SMEM_BYTES);
    cudaFuncSetAttribute(av_tf32x3,
        cudaFuncAttributeMaxDynamicSharedMemorySize, SMEM_BYTES);

    // 1) RPE table
    {
        int n = HH * NT * DD;
        cp_kernel<<<(n + 255) / 256, 256>>>(rel_h, rel_w);
    }
    // 2) QKV projections
    {
        dim3 grid(MM / 128, CC / 112, 3);
        proj_tf32x3<0><<<grid, 256, SMEM_BYTES>>>(x, Wq, Wk, Wv, bq, bk, bv,
                                                  nullptr);
    }
    // 3) scores
    {
        dim3 grid(2, 2, BH);
        scores_tf32x3<<<grid, 256, SMEM_BYTES>>>();
    }
    // 4) softmax
    softmax_kernel<<<(BH * NT) / 8, 256>>>();
    // 5) attn @ V
    {
        dim3 grid(2, 2, BH);
        av_tf32x3<<<grid, 256, SMEM_BYTES>>>();
    }
    // 6) output projection
    {
        dim3 grid(MM / 128, CC / 112, 1);
        proj_tf32x3<1><<<grid, 256, SMEM_BYTES>>>(nullptr, Wo, nullptr,
                                                  nullptr, bo, nullptr,
                                                  nullptr, out);
    }
}

// round 10
// speedup vs baseline: 2.4001x; 2.0385x over previous
#include <cuda_runtime.h>
#include <cstdint>

// Problem constants
#define BB 256
#define NT 196
#define CC 784
#define HH 4
#define DD 196
#define MM (BB*NT)      // 50176
#define BH (BB*HH)      // 1024

// ---------------------------------------------------------------------------
// Scratch (static __device__ — no allocations allowed). All plain fp32.
// ---------------------------------------------------------------------------
__device__ float g_q[(size_t)BH*NT*DD];   // (b,h,n,d)
__device__ float g_k[(size_t)BH*NT*DD];
__device__ float g_v[(size_t)BH*NT*DD];
__device__ float g_s[(size_t)BH*NT*NT];   // scores -> attn (in place)
__device__ float g_o[(size_t)BB*NT*CC];   // (b,n,h*d)
__device__ float g_cp[(size_t)HH*NT*DD];  // cp[h][p][k]

// ---------------------------------------------------------------------------
// bf16 2-term split helpers
//   v = hi + lo, hi = bf16(v), lo = bf16(v - hi); products hh + hl + lh.
//   Words are bf16x2 k-pairs: low half = even k, high half = odd k.
// ---------------------------------------------------------------------------
__device__ __forceinline__ void splitpair(float x, float y,
                                          uint32_t& hi, uint32_t& lo) {
    uint32_t h;
    asm("cvt.rn.bf16x2.f32 %0, %1, %2;" : "=r"(h) : "f"(y), "f"(x));
    float hx = __uint_as_float(h << 16);
    float hy = __uint_as_float(h & 0xffff0000u);
    asm("cvt.rn.bf16x2.f32 %0, %1, %2;" : "=r"(lo) : "f"(y - hy), "f"(x - hx));
    hi = h;
}
__device__ __forceinline__ void split4p(float4 v, uint2& hi, uint2& lo) {
    splitpair(v.x, v.y, hi.x, lo.x);
    splitpair(v.z, v.w, hi.y, lo.y);
}
__device__ __forceinline__ void mmabf(float* c, const uint32_t* a,
                                      uint32_t b0, uint32_t b1) {
    asm volatile("mma.sync.aligned.m16n8k16.row.col.f32.bf16.bf16.f32 "
                 "{%0,%1,%2,%3}, {%4,%5,%6,%7}, {%8,%9}, {%0,%1,%2,%3};"
                 : "+f"(c[0]), "+f"(c[1]), "+f"(c[2]), "+f"(c[3])
                 : "r"(a[0]), "r"(a[1]), "r"(a[2]), "r"(a[3]),
                   "r"(b0), "r"(b1));
}

// Smem tile row layout (uint32 words, stride 20):
//   words 0..7  : hi bf16x2 pairs for k=0..15
//   words 8..15 : lo bf16x2 pairs
//   words 16..19: pad (conflict-free fragment reads)
// One BK=16 chunk: warp tile 32(M) x 56(N) = 2 m16 x 7 n8 frags, 3 products.
__device__ __forceinline__ void gemm_bk16_bf(const uint32_t (*A)[20],
                                             const uint32_t (*B)[20],
                                             int wm, int wn, int g, int t,
                                             float acc[2][7][4]) {
    uint32_t ah[2][4], al[2][4];
#pragma unroll
    for (int mt = 0; mt < 2; ++mt) {
        const uint32_t* r0 = A[wm + mt * 16 + g];
        const uint32_t* r1 = A[wm + mt * 16 + g + 8];
        ah[mt][0] = r0[t];      ah[mt][1] = r1[t];
        ah[mt][2] = r0[t + 4];  ah[mt][3] = r1[t + 4];
        al[mt][0] = r0[8 + t];     al[mt][1] = r1[8 + t];
        al[mt][2] = r0[12 + t];    al[mt][3] = r1[12 + t];
    }
#pragma unroll
    for (int nt = 0; nt < 7; ++nt) {
        const uint32_t* bc = B[wn + nt * 8 + g];
        uint32_t b0h = bc[t], b1h = bc[t + 4];
        uint32_t b0l = bc[8 + t], b1l = bc[12 + t];
#pragma unroll
        for (int mt = 0; mt < 2; ++mt) {
            mmabf(acc[mt][nt], ah[mt], b0h, b1h);   // hi*hi
            mmabf(acc[mt][nt], ah[mt], b0l, b1l);   // hi*lo
            mmabf(acc[mt][nt], al[mt], b0h, b1h);   // lo*hi
        }
    }
}

// Store a row's 4 consecutive k values (split) into a tile row.
__device__ __forceinline__ void st_row(uint32_t (*S)[20], int row, int wq,
                                       float4 v) {
    uint2 h, l;
    split4p(v, h, l);
    *(uint2*)&S[row][wq] = h;
    *(uint2*)&S[row][8 + wq] = l;
}

// Guarded row-major float4 load from a 196-wide matrix (row pre-clamped).
__device__ __forceinline__ float4 load_row196(const float* P, int row, int k,
                                              bool kval) {
    if (kval) return *(const float4*)&P[(size_t)row * 196 + k];
    return make_float4(0.f, 0.f, 0.f, 0.f);
}

// Transposed tile gather (16k x 112n from 196-wide P), k-pair oriented:
// 224 units; unit = (kp 0..7, nq 0..27): rows k0+2kp, k0+2kp+1, cols nq*4..+3.
__device__ __forceinline__ void load_trans_bf(const float* P, int j0, int k0,
                                              int tid, float* pv) {
    if (tid < 224) {
        int kp = tid / 28, nq = tid % 28;
        int kr0 = k0 + 2 * kp, kr1 = kr0 + 1;
        int n = j0 + nq * 4;
        if (kr1 < 196 && n + 3 < 196) {
            float4 a = *(const float4*)&P[(size_t)kr0 * 196 + n];
            float4 b = *(const float4*)&P[(size_t)kr1 * 196 + n];
            pv[0] = a.x; pv[1] = a.y; pv[2] = a.z; pv[3] = a.w;
            pv[4] = b.x; pv[5] = b.y; pv[6] = b.z; pv[7] = b.w;
        } else {
#pragma unroll
            for (int j = 0; j < 4; ++j) {
                pv[j]     = (kr0 < 196 && n + j < 196)
                            ? P[(size_t)kr0 * 196 + n + j] : 0.f;
                pv[4 + j] = (kr1 < 196 && n + j < 196)
                            ? P[(size_t)kr1 * 196 + n + j] : 0.f;
            }
        }
    }
}
__device__ __forceinline__ void store_trans_bf(uint32_t (*Bsb)[20], int tid,
                                               const float* pv) {
    if (tid < 224) {
        int kp = tid / 28, nq = tid % 28;
#pragma unroll
        for (int j = 0; j < 4; ++j) {
            uint32_t h, l;
            splitpair(pv[j], pv[4 + j], h, l);
            Bsb[nq * 4 + j][kp] = h;
            Bsb[nq * 4 + j][8 + kp] = l;
        }
    }
}

// cp[h][p][k] = rel_h[h][k][p/14] + rel_w[h][k][p%14]
__global__ void cp_kernel(const float* __restrict__ rel_h,
                          const float* __restrict__ rel_w) {
    int idx = blockIdx.x * blockDim.x + threadIdx.x;
    if (idx >= HH * NT * DD) return;
    int k = idx % DD;
    int p = (idx / DD) % NT;
    int h = idx / (DD * NT);
    g_cp[idx] = rel_h[(h * DD + k) * 14 + p / 14]
              + rel_w[(h * DD + k) * 14 + p % 14];
}

// ---------------------------------------------------------------------------
// Projection GEMM (bf16x2 split): out = A(M x 784) @ W(784 x 784)^T + bias
// Block 128x112, BK=16, 256 threads (8 warps 4x2), double-buffered.
// MODE 0: A=x, z selects (W,bias,dst q/k/v) head-split scatter.
// MODE 1: A=g_o, plain store to d_out.
// ---------------------------------------------------------------------------
template <int MODE>
__global__ __launch_bounds__(256)
void proj_bf(const float* __restrict__ Ain,
             const float* __restrict__ W0, const float* __restrict__ W1,
             const float* __restrict__ W2,
             const float* __restrict__ b0p, const float* __restrict__ b1p,
             const float* __restrict__ b2p, float* __restrict__ outp) {
    __shared__ uint32_t As[2][128][20];
    __shared__ uint32_t Bs[2][112][20];

    const int tid = threadIdx.x;
    const int z = (MODE == 0) ? blockIdx.z : 0;
    const float* A = (MODE == 0) ? Ain : g_o;
    const float* W = (MODE == 0) ? ((z == 0) ? W0 : (z == 1) ? W1 : W2) : W0;
    const float* bias = (MODE == 0) ? ((z == 0) ? b0p : (z == 1) ? b1p : b2p)
                                    : b0p;
    float* dst = (MODE == 0) ? ((z == 0) ? g_q : (z == 1) ? g_k : g_v) : outp;

    const int m0 = blockIdx.x * 128, n0 = blockIdx.y * 112;
    const int w = tid >> 5, lane = tid & 31;
    const int wm = (w >> 1) * 32, wn = (w & 1) * 56;
    const int g = lane >> 2, t = lane & 3;

    const int rowA0 = tid >> 2, kq = (tid & 3) * 4, wq = (tid & 3) * 2;
    const int rowA1 = (tid + 256) >> 2;
    const bool hasB1 = (tid + 256) < 448;

    float acc[2][7][4];
#pragma unroll
    for (int i = 0; i < 2; i++)
#pragma unroll
        for (int j = 0; j < 7; j++)
#pragma unroll
            for (int c = 0; c < 4; c++) acc[i][j][c] = 0.f;

    // prologue: tile 0 -> buf 0
    {
        st_row(As[0], rowA0, wq,
               *(const float4*)&A[(size_t)(m0 + rowA0) * 784 + kq]);
        st_row(As[0], rowA1, wq,
               *(const float4*)&A[(size_t)(m0 + rowA1) * 784 + kq]);
        st_row(Bs[0], rowA0, wq,
               *(const float4*)&W[(size_t)(n0 + rowA0) * 784 + kq]);
        if (hasB1)
            st_row(Bs[0], rowA1, wq,
                   *(const float4*)&W[(size_t)(n0 + rowA1) * 784 + kq]);
    }
    __syncthreads();

    for (int it = 0; it < 49; ++it) {
        const int bf = it & 1;
        float4 va0, va1, vb0, vb1;
        if (it < 48) {
            int k0 = (it + 1) * 16;
            va0 = *(const float4*)&A[(size_t)(m0 + rowA0) * 784 + k0 + kq];
            va1 = *(const float4*)&A[(size_t)(m0 + rowA1) * 784 + k0 + kq];
            vb0 = *(const float4*)&W[(size_t)(n0 + rowA0) * 784 + k0 + kq];
            if (hasB1)
                vb1 = *(const float4*)&W[(size_t)(n0 + rowA1) * 784 + k0 + kq];
        }
        gemm_bk16_bf(As[bf], Bs[bf], wm, wn, g, t, acc);
        if (it < 48) {
            const int nb = bf ^ 1;
            st_row(As[nb], rowA0, wq, va0);
            st_row(As[nb], rowA1, wq, va1);
            st_row(Bs[nb], rowA0, wq, vb0);
            if (hasB1) st_row(Bs[nb], rowA1, wq, vb1);
        }
        __syncthreads();
    }

    // epilogue
#pragma unroll
    for (int mt = 0; mt < 2; ++mt) {
#pragma unroll
        for (int nt = 0; nt < 7; ++nt) {
            int col = n0 + wn + nt * 8 + 2 * t;
            float bv0 = bias[col], bv1 = bias[col + 1];
#pragma unroll
            for (int half = 0; half < 2; ++half) {
                int row = m0 + wm + mt * 16 + g + half * 8;
                float v0 = acc[mt][nt][half * 2 + 0] + bv0;
                float v1 = acc[mt][nt][half * 2 + 1] + bv1;
                if (MODE == 0) {
                    int bi = row / 196, n = row % 196;
                    int h0 = col / 196, d0c = col % 196;
                    int h1 = (col + 1) / 196, d1c = (col + 1) % 196;
                    dst[(((size_t)bi * 4 + h0) * 196 + n) * 196 + d0c] = v0;
                    dst[(((size_t)bi * 4 + h1) * 196 + n) * 196 + d1c] = v1;
                } else {
                    dst[(size_t)row * 784 + col]     = v0;
                    dst[(size_t)row * 784 + col + 1] = v1;
                }
            }
        }
    }
}

// ---------------------------------------------------------------------------
// Scores (bf16x2 split): S = Q K^T / 14 + Cp @ Q, per (b,h) 196x196.
// ---------------------------------------------------------------------------
__global__ __launch_bounds__(256)
void scores_bf() {
    __shared__ uint32_t As[2][128][20];
    __shared__ uint32_t Bs[2][112][20];

    const int batch = blockIdx.z, h = batch & 3;
    const int i0 = blockIdx.y * 128, j0 = blockIdx.x * 112;
    const float* Q  = g_q  + (size_t)batch * 196 * 196;
    const float* Kp = g_k  + (size_t)batch * 196 * 196;
    const float* CP = g_cp + (size_t)h * 196 * 196;

    const int tid = threadIdx.x;
    const int w = tid >> 5, lane = tid & 31;
    const int wm = (w >> 1) * 32, wn = (w & 1) * 56;
    const int g = lane >> 2, t = lane & 3;

    const int rowA0 = tid >> 2, kq = (tid & 3) * 4, wq = (tid & 3) * 2;
    const int rowA1 = (tid + 256) >> 2;
    const bool hasB1 = (tid + 256) < 448;
    const int arA0 = min(i0 + rowA0, 195), arA1 = min(i0 + rowA1, 195);
    const int brA0 = min(j0 + rowA0, 195), brA1 = min(j0 + rowA1, 195);

    float acc[2][7][4];
#pragma unroll
    for (int i = 0; i < 2; i++)
#pragma unroll
        for (int j = 0; j < 7; j++)
#pragma unroll
            for (int c = 0; c < 4; c++) acc[i][j][c] = 0.f;

    // ---------------- pass 1: Q K^T ----------------
    {
        st_row(As[0], rowA0, wq, load_row196(Q, arA0, kq, true));
        st_row(As[0], rowA1, wq, load_row196(Q, arA1, kq, true));
        st_row(Bs[0], rowA0, wq, load_row196(Kp, brA0, kq, true));
        if (hasB1) st_row(Bs[0], rowA1, wq, load_row196(Kp, brA1, kq, true));
    }
    __syncthreads();
    for (int it = 0; it < 13; ++it) {
        const int bf = it & 1;
        float4 va0, va1, vb0, vb1;
        if (it < 12) {
            int k0 = (it + 1) * 16;
            bool kv = (k0 + kq) < 196;
            va0 = load_row196(Q, arA0, k0 + kq, kv);
            va1 = load_row196(Q, arA1, k0 + kq, kv);
            vb0 = load_row196(Kp, brA0, k0 + kq, kv);
            if (hasB1) vb1 = load_row196(Kp, brA1, k0 + kq, kv);
        }
        gemm_bk16_bf(As[bf], Bs[bf], wm, wn, g, t, acc);
        if (it < 12) {
            const int nb = bf ^ 1;
            st_row(As[nb], rowA0, wq, va0);
            st_row(As[nb], rowA1, wq, va1);
            st_row(Bs[nb], rowA0, wq, vb0);
            if (hasB1) st_row(Bs[nb], rowA1, wq, vb1);
        }
        __syncthreads();
    }

    const float inv14 = 1.0f / 14.0f;
#pragma unroll
    for (int i = 0; i < 2; i++)
#pragma unroll
        for (int j = 0; j < 7; j++)
#pragma unroll
            for (int c = 0; c < 4; c++) acc[i][j][c] *= inv14;

    __syncthreads();

    // ---------------- pass 2: Cp @ Q (contraction over tokens) ------------
    {
        float pv[8];
        st_row(As[0], rowA0, wq, load_row196(CP, arA0, kq, true));
        st_row(As[0], rowA1, wq, load_row196(CP, arA1, kq, true));
        load_trans_bf(Q, j0, 0, tid, pv);
        store_trans_bf(Bs[0], tid, pv);
    }
    __syncthreads();
    for (int it = 0; it < 13; ++it) {
        const int bf = it & 1;
        float4 va0, va1;
        float pv[8];
        if (it < 12) {
            int k0 = (it + 1) * 16;
            bool kv = (k0 + kq) < 196;
            va0 = load_row196(CP, arA0, k0 + kq, kv);
            va1 = load_row196(CP, arA1, k0 + kq, kv);
            load_trans_bf(Q, j0, k0, tid, pv);
        }
        gemm_bk16_bf(As[bf], Bs[bf], wm, wn, g, t, acc);
        if (it < 12) {
            const int nb = bf ^ 1;
            st_row(As[nb], rowA0, wq, va0);
            st_row(As[nb], rowA1, wq, va1);
            store_trans_bf(Bs[nb], tid, pv);
        }
        __syncthreads();
    }

    float* S = g_s + (size_t)batch * 196 * 196;
#pragma unroll
    for (int mt = 0; mt < 2; ++mt) {
#pragma unroll
        for (int nt = 0; nt < 7; ++nt) {
            int col = j0 + wn + nt * 8 + 2 * t;
#pragma unroll
            for (int half = 0; half < 2; ++half) {
                int row = i0 + wm + mt * 16 + g + half * 8;
                if (row < 196) {
                    if (col < 196)
                        S[(size_t)row * 196 + col] = acc[mt][nt][half*2+0];
                    if (col + 1 < 196)
                        S[(size_t)row * 196 + col + 1] = acc[mt][nt][half*2+1];
                }
            }
        }
    }
}

// ---------------------------------------------------------------------------
// Row-wise softmax, one warp per row. Plain fp32 in/out.
// ---------------------------------------------------------------------------
__global__ __launch_bounds__(256)
void softmax_kernel() {
    int row  = blockIdx.x * 8 + (threadIdx.x >> 5);
    int lane = threadIdx.x & 31;
    if (row >= BH * NT) return;
    float* S = g_s + (size_t)row * 196;

    float vals[7];
    float mx = -1e30f;
#pragma unroll
    for (int s = 0; s < 7; s++) {
        int j = lane + 32 * s;
        vals[s] = (j < 196) ? S[j] : -1e30f;
        mx = fmaxf(mx, vals[s]);
    }
#pragma unroll
    for (int off = 16; off > 0; off >>= 1)
        mx = fmaxf(mx, __shfl_xor_sync(0xffffffffu, mx, off));

    float sum = 0.f;
#pragma unroll
    for (int s = 0; s < 7; s++) {
        vals[s] = expf(vals[s] - mx);
        sum += vals[s];
    }
#pragma unroll
    for (int off = 16; off > 0; off >>= 1)
        sum += __shfl_xor_sync(0xffffffffu, sum, off);

    float inv = 1.0f / sum;
#pragma unroll
    for (int s = 0; s < 7; s++) {
        int j = lane + 32 * s;
        if (j < 196) S[j] = vals[s] * inv;
    }
}

// ---------------------------------------------------------------------------
// attn @ V (bf16x2 split), head-merged fp32 store into g_o.
// ---------------------------------------------------------------------------
__global__ __launch_bounds__(256)
void av_bf() {
    __shared__ uint32_t As[2][128][20];
    __shared__ uint32_t Bs[2][112][20];

    const int batch = blockIdx.z;
    const int bi = batch >> 2, h = batch & 3;
    const int i0 = blockIdx.y * 128, d0 = blockIdx.x * 112;
    const float* Sb = g_s + (size_t)batch * 196 * 196;
    const float* V  = g_v + (size_t)batch * 196 * 196;

    const int tid = threadIdx.x;
    const int w = tid >> 5, lane = tid & 31;
    const int wm = (w >> 1) * 32, wn = (w & 1) * 56;
    const int g = lane >> 2, t = lane & 3;

    const int rowA0 = tid >> 2, kq = (tid & 3) * 4, wq = (tid & 3) * 2;
    const int rowA1 = (tid + 256) >> 2;
    const int arA0 = min(i0 + rowA0, 195), arA1 = min(i0 + rowA1, 195);

    float acc[2][7][4];
#pragma unroll
    for (int i = 0; i < 2; i++)
#pragma unroll
        for (int j = 0; j < 7; j++)
#pragma unroll
            for (int c = 0; c < 4; c++) acc[i][j][c] = 0.f;

    {
        float pv[8];
        st_row(As[0], rowA0, wq, load_row196(Sb, arA0, kq, true));
        st_row(As[0], rowA1, wq, load_row196(Sb, arA1, kq, true));
        load_trans_bf(V, d0, 0, tid, pv);
        store_trans_bf(Bs[0], tid, pv);
    }
    __syncthreads();
    for (int it = 0; it < 13; ++it) {
        const int bf = it & 1;
        float4 va0, va1;
        float pv[8];
        if (it < 12) {
            int k0 = (it + 1) * 16;
            bool kv = (k0 + kq) < 196;
            va0 = load_row196(Sb, arA0, k0 + kq, kv);
            va1 = load_row196(Sb, arA1, k0 + kq, kv);
            load_trans_bf(V, d0, k0, tid, pv);
        }
        gemm_bk16_bf(As[bf], Bs[bf], wm, wn, g, t, acc);
        if (it < 12) {
            const int nb = bf ^ 1;
            st_row(As[nb], rowA0, wq, va0);
            st_row(As[nb], rowA1, wq, va1);
            store_trans_bf(Bs[nb], tid, pv);
        }
        __syncthreads();
    }

#pragma unroll
    for (int mt = 0; mt < 2; ++mt) {
#pragma unroll
        for (int nt = 0; nt < 7; ++nt) {
            int col = d0 + wn + nt * 8 + 2 * t;
#pragma unroll
            for (int half = 0; half < 2; ++half) {
                int row = i0 + wm + mt * 16 + g + half * 8;
                if (row < 196) {
                    if (col < 196)
                        g_o[((size_t)bi * 196 + row) * 784 + h * 196 + col]
                            = acc[mt][nt][half*2+0];
                    if (col + 1 < 196)
                        g_o[((size_t)bi * 196 + row) * 784 + h * 196 + col + 1]
                            = acc[mt][nt][half*2+1];
                }
            }
        }
    }
}

// ---------------------------------------------------------------------------
// kernel_launch
// ---------------------------------------------------------------------------
extern "C" void kernel_launch(void* const* d_in, const int* in_sizes, int n_in,
                              void* d_out, int out_size) {
    const float* x     = (const float*)d_in[0];
    const float* Wq    = (const float*)d_in[1];
    const float* bq    = (const float*)d_in[2];
    const float* Wk    = (const float*)d_in[3];
    const float* bk    = (const float*)d_in[4];
    const float* Wv    = (const float*)d_in[5];
    const float* bv    = (const float*)d_in[6];
    const float* Wo    = (const float*)d_in[7];
    const float* bo    = (const float*)d_in[8];
    const float* rel_h = (const float*)d_in[9];
    const float* rel_w = (const float*)d_in[10];
    float* out = (float*)d_out;

    // 1) RPE table
    {
        int n = HH * NT * DD;
        cp_kernel<<<(n + 255) / 256, 256>>>(rel_h, rel_w);
    }
    // 2) QKV projections
    {
        dim3 grid(MM / 128, CC / 112, 3);
        proj_bf<0><<<grid, 256>>>(x, Wq, Wk, Wv, bq, bk, bv, nullptr);
    }
    // 3) scores
    {
        dim3 grid(2, 2, BH);
        scores_bf<<<grid, 256>>>();
    }
    // 4) softmax
    softmax_kernel<<<(BH * NT) / 8, 256>>>();
    // 5) attn @ V
    {
        dim3 grid(2, 2, BH);
        av_bf<<<grid, 256>>>();
    }
    // 6) output projection
    {
        dim3 grid(MM / 128, CC / 112, 1);
        proj_bf<1><<<grid, 256>>>(nullptr, Wo, nullptr, nullptr, bo, nullptr,
                                  nullptr, out);
    }
}